// round 4
// baseline (speedup 1.0000x reference)
#include <cuda_runtime.h>
#include <cuda.h>
#include <cuda_fp16.h>
#include <cstdint>

// ================= problem dims =================
#define P_DIM 2048
#define Q_DIM 2048
#define NBATCH 16
#define T_DIM 256
#define K_HALF (NBATCH * T_DIM)   // 4096
#define K_TOT  (2 * K_HALF)       // 8192

// ================= gemm config (shared by both paths) =================
#define TILE_M 128
#define TILE_N 128
#define CHUNK_K 64                  // halves per k-chunk = 128 bytes per row
#define NCHUNK (K_TOT / CHUNK_K)    // 128
#define NSTAGE 3
#define A_TILE_BYTES (TILE_M * 128) // 16384
#define B_TILE_BYTES (TILE_N * 128) // 16384
#define STAGE_BYTES (A_TILE_BYTES + B_TILE_BYTES)   // 32768
#define SMEM_DATA0 1024
#define SMEM_DYN_BYTES (SMEM_DATA0 + NSTAGE * STAGE_BYTES)  // 99328

// trace constants: exp(-0.001/0.02), exp(-0.001/0.101)
#define DECAY_PM 0.95122942450071400f
#define DECAY_X  0.99014786313283800f
#define A_TRIPLET 0.0065f

#if defined(__CUDA_ARCH_FEAT_SM103_ALL) || defined(__CUDA_ARCH_FEAT_SM100_ALL)
#define HAS_TCGEN05 1
#endif

// ============ static device scratch (no allocs allowed) ============
__device__ __half g_A[(size_t)P_DIM * K_TOT];   // [P, 8192]: [x_pre | pre]
__device__ __half g_B[(size_t)Q_DIM * K_TOT];   // [Q, 8192]: [post*(Ap+c*xt) | -Am*x_post]
__device__ unsigned int g_spike_count;

// ============ helpers ============
__device__ __forceinline__ uint32_t smem_u32(const void* p) {
    uint32_t a;
    asm("{ .reg .u64 t; cvta.to.shared.u64 t, %1; cvt.u32.u64 %0, t; }" : "=r"(a) : "l"(p));
    return a;
}
__device__ __forceinline__ uint32_t pack_h2(float lo, float hi) {
    __half2 h = __floats2half2_rn(lo, hi);
    return *reinterpret_cast<uint32_t*>(&h);
}

// ================= kernel 0: zero the spike counter =================
__global__ void zero_count_kernel() { g_spike_count = 0u; }

// ================= kernel 1: traces + operand packing =================
__global__ void __launch_bounds__(256) traces_kernel(
    const float* __restrict__ pre,
    const float* __restrict__ post,
    const float* __restrict__ apP,
    const float* __restrict__ amP)
{
    int idx = blockIdx.x * blockDim.x + threadIdx.x;   // 0..65535
    bool is_pre = idx < (NBATCH * P_DIM);
    int li = is_pre ? idx : idx - NBATCH * P_DIM;
    int n = li & (P_DIM - 1);
    int b = li >> 11;
    const float4* in4 = (const float4*)((is_pre ? pre : post) + ((size_t)(b * P_DIM + n) << 8));
    __half* o1 = (is_pre ? g_A : g_B) + (size_t)n * K_TOT + b * T_DIM;
    __half* o2 = o1 + K_HALF;
    unsigned cnt = 0;

    if (is_pre) {
        float x = 0.f;
        #pragma unroll 4
        for (int t8 = 0; t8 < T_DIM / 8; t8++) {
            float4 f0 = in4[2 * t8], f1 = in4[2 * t8 + 1];
            float fv[8] = {f0.x, f0.y, f0.z, f0.w, f1.x, f1.y, f1.z, f1.w};
            float xa[8];
            #pragma unroll
            for (int i = 0; i < 8; i++) {
                float s = fv[i];
                xa[i] = x;
                cnt += (s > 0.5f) ? 1u : 0u;
                x = DECAY_PM * (x + s);
            }
            uint4 ua, ub;
            ua.x = pack_h2(xa[0], xa[1]); ua.y = pack_h2(xa[2], xa[3]);
            ua.z = pack_h2(xa[4], xa[5]); ua.w = pack_h2(xa[6], xa[7]);
            ub.x = pack_h2(fv[0], fv[1]); ub.y = pack_h2(fv[2], fv[3]);
            ub.z = pack_h2(fv[4], fv[5]); ub.w = pack_h2(fv[6], fv[7]);
            *(uint4*)(o1 + t8 * 8) = ua;      // x_pre trace
            *(uint4*)(o2 + t8 * 8) = ub;      // raw pre spikes (exact in fp16)
        }
    } else {
        float Ap = *apP;
        float Am = *amP;
        float xm = 0.f, xt = 0.f;
        #pragma unroll 4
        for (int t8 = 0; t8 < T_DIM / 8; t8++) {
            float4 f0 = in4[2 * t8], f1 = in4[2 * t8 + 1];
            float fv[8] = {f0.x, f0.y, f0.z, f0.w, f1.x, f1.y, f1.z, f1.w};
            float v1[8], v2[8];
            #pragma unroll
            for (int i = 0; i < 8; i++) {
                float s = fv[i];
                v1[i] = s * (Ap + A_TRIPLET * xt);   // ltp + triplet coefficient
                v2[i] = -Am * xm;                    // -ltd coefficient
                cnt += (s > 0.5f) ? 1u : 0u;
                xm = DECAY_PM * (xm + s);
                xt = DECAY_X * (xt + s);
            }
            uint4 ua, ub;
            ua.x = pack_h2(v1[0], v1[1]); ua.y = pack_h2(v1[2], v1[3]);
            ua.z = pack_h2(v1[4], v1[5]); ua.w = pack_h2(v1[6], v1[7]);
            ub.x = pack_h2(v2[0], v2[1]); ub.y = pack_h2(v2[2], v2[3]);
            ub.z = pack_h2(v2[4], v2[5]); ub.w = pack_h2(v2[6], v2[7]);
            *(uint4*)(o1 + t8 * 8) = ua;
            *(uint4*)(o2 + t8 * 8) = ub;
        }
    }
    #pragma unroll
    for (int o = 16; o; o >>= 1) cnt += __shfl_xor_sync(0xffffffffu, cnt, o);
    if ((threadIdx.x & 31) == 0 && cnt) atomicAdd(&g_spike_count, cnt);
}

// ================= mma.sync building blocks (sm_80-compatible PTX) =============
__device__ __forceinline__ void ldsm4(uint32_t& r0, uint32_t& r1, uint32_t& r2, uint32_t& r3,
                                      uint32_t addr) {
    asm volatile("ldmatrix.sync.aligned.m8n8.x4.shared.b16 {%0,%1,%2,%3}, [%4];"
                 : "=r"(r0), "=r"(r1), "=r"(r2), "=r"(r3) : "r"(addr));
}
__device__ __forceinline__ void mma16816(float* d, const uint32_t* a, uint32_t b0, uint32_t b1) {
    asm volatile(
        "mma.sync.aligned.m16n8k16.row.col.f32.f16.f16.f32 "
        "{%0,%1,%2,%3}, {%4,%5,%6,%7}, {%8,%9}, {%0,%1,%2,%3};"
        : "+f"(d[0]), "+f"(d[1]), "+f"(d[2]), "+f"(d[3])
        : "r"(a[0]), "r"(a[1]), "r"(a[2]), "r"(a[3]), "r"(b0), "r"(b1));
}
__device__ __forceinline__ void cpasync16(uint32_t dst, const void* src) {
    asm volatile("cp.async.cg.shared.global [%0], [%1], 16;" :: "r"(dst), "l"(src));
}

// ================= tcgen05 building blocks (compiled only when "a"-target) =====
#ifdef HAS_TCGEN05
// idesc kind::f16: f16 in (atype=btype=0), f32 accum, M=128, N=128
#define MMA_IDESC_F16 ((1u<<4) | ((TILE_N/8u)<<17) | ((TILE_M/16u)<<24))
static constexpr uint64_t DESC_BASE =
    (uint64_t(2) << 61) | (uint64_t(1) << 46) | (uint64_t(64) << 32) | (uint64_t(1) << 16);
__device__ __forceinline__ void mbar_init(uint32_t a, uint32_t n) {
    asm volatile("mbarrier.init.shared.b64 [%0], %1;" :: "r"(a), "r"(n) : "memory");
}
__device__ __forceinline__ void mbar_expect_tx(uint32_t a, uint32_t bytes) {
    asm volatile("mbarrier.arrive.expect_tx.shared.b64 _, [%0], %1;" :: "r"(a), "r"(bytes) : "memory");
}
__device__ __forceinline__ void mbar_wait(uint32_t a, uint32_t ph) {
    asm volatile(
        "{\n\t.reg .pred P;\n\t"
        "W_%=:\n\t"
        "mbarrier.try_wait.parity.acquire.cta.shared::cta.b64 P, [%0], %1, 0x989680;\n\t"
        "@P bra.uni D_%=;\n\tbra.uni W_%=;\n\tD_%=:\n\t}"
        :: "r"(a), "r"(ph) : "memory");
}
__device__ __forceinline__ void tma_2d(uint32_t dst, const CUtensorMap* m, int x, int y, uint32_t mb) {
    asm volatile(
        "cp.async.bulk.tensor.2d.shared::cta.global.tile.mbarrier::complete_tx::bytes "
        "[%0], [%1, {%2, %3}], [%4];"
        :: "r"(dst), "l"(m), "r"(x), "r"(y), "r"(mb) : "memory");
}
__device__ __forceinline__ void mma_ss_f16(uint32_t d, uint64_t ad, uint64_t bd, uint32_t acc) {
    asm volatile(
        "{\n\t.reg .pred p;\n\tsetp.ne.u32 p, %4, 0;\n\t"
        "tcgen05.mma.cta_group::1.kind::f16 [%0], %1, %2, %3, {%5, %5, %5, %5}, p;\n\t}"
        :: "r"(d), "l"(ad), "l"(bd), "r"(MMA_IDESC_F16), "r"(acc), "r"(0u) : "memory");
}
#endif

// ================= kernel 2: GEMM + fused epilogue =================
// grid (16,16) = 256 CTAs, 128 threads. D[p,q] = A[p,:].B[q,:]^T over K=8192.
// out = clip(weights + D * scale, -2, 2)
__global__ void __launch_bounds__(128) stdp_gemm_kernel(
    const __grid_constant__ CUtensorMap tmA,
    const __grid_constant__ CUtensorMap tmB,
    const float* __restrict__ weights,
    float* __restrict__ out)
{
    extern __shared__ __align__(1024) char smem[];
    uint32_t sb = smem_u32(smem);
    int tid = threadIdx.x;
    int wid = tid >> 5, lane = tid & 31;
    int m0 = blockIdx.x * TILE_M;
    int q0 = blockIdx.y * TILE_N;

#ifdef HAS_TCGEN05
    // -------- tcgen05 path (active only if toolchain compiled the "a" target) ----
    if (wid == 0) {
        asm volatile("tcgen05.alloc.cta_group::1.sync.aligned.shared::cta.b32 [%0], %1;"
                     :: "r"(sb), "r"(128u) : "memory");
    }
    if (tid == 0) {
        #pragma unroll
        for (int s = 0; s < NSTAGE; s++) { mbar_init(sb + 8 + 8*s, 1); mbar_init(sb + 40 + 8*s, 1); }
        asm volatile("fence.proxy.async.shared::cta;" ::: "memory");
    }
    __syncthreads();
    uint32_t tmem;
    asm volatile("ld.shared.b32 %0, [%1];" : "=r"(tmem) : "r"(sb));

    if (tid == 0) {
        #pragma unroll
        for (int s = 0; s < NSTAGE; s++) {
            uint32_t stage = sb + SMEM_DATA0 + s * STAGE_BYTES;
            mbar_expect_tx(sb + 8 + 8*s, STAGE_BYTES);
            tma_2d(stage,                &tmA, s * CHUNK_K, m0, sb + 8 + 8*s);
            tma_2d(stage + A_TILE_BYTES, &tmB, s * CHUNK_K, q0, sb + 8 + 8*s);
        }
        int s = 0;
        for (int c = 0; c < NCHUNK; c++) {
            uint32_t ph = (uint32_t)((c / NSTAGE) & 1);
            uint32_t full = sb + 8 + 8*s, done = sb + 40 + 8*s;
            mbar_wait(full, ph);
            uint32_t stage = sb + SMEM_DATA0 + s * STAGE_BYTES;
            uint64_t ad = DESC_BASE | ((uint64_t)(stage >> 4) & 0x3FFF);
            uint64_t bd = DESC_BASE | ((uint64_t)((stage + A_TILE_BYTES) >> 4) & 0x3FFF);
            #pragma unroll
            for (int j = 0; j < 4; j++)
                mma_ss_f16(tmem, ad + 2*j, bd + 2*j, (uint32_t)((c | j) != 0));
            asm volatile("tcgen05.commit.cta_group::1.mbarrier::arrive::one.shared::cluster.b64 [%0];"
                         :: "r"(done) : "memory");
            if (c + NSTAGE < NCHUNK) {
                mbar_wait(done, ph);
                mbar_expect_tx(full, STAGE_BYTES);
                tma_2d(stage,                &tmA, (c + NSTAGE) * CHUNK_K, m0, full);
                tma_2d(stage + A_TILE_BYTES, &tmB, (c + NSTAGE) * CHUNK_K, q0, full);
            }
            s = (s + 1 == NSTAGE) ? 0 : s + 1;
        }
        mbar_wait(sb + 40 + 8 * ((NCHUNK - 1) % NSTAGE), (uint32_t)(((NCHUNK - 1) / NSTAGE) & 1));
    }
    __syncthreads();
    asm volatile("tcgen05.fence::after_thread_sync;" ::: "memory");

    float act = (float)g_spike_count * (1.0f / (NBATCH * T_DIM));
    float scale = sqrtf(0.1f / (act + 1e-6f));
    int p = m0 + wid * 32 + lane;
    const float4* w4 = (const float4*)(weights + (size_t)p * Q_DIM + q0);
    float4* o4 = (float4*)(out + (size_t)p * Q_DIM + q0);
    #pragma unroll 1
    for (int cb = 0; cb < TILE_N / 32; cb++) {
        uint32_t r[32];
        asm volatile(
            "tcgen05.ld.sync.aligned.32x32b.x32.b32 "
            "{%0,%1,%2,%3,%4,%5,%6,%7,%8,%9,%10,%11,%12,%13,%14,%15,"
            "%16,%17,%18,%19,%20,%21,%22,%23,%24,%25,%26,%27,%28,%29,%30,%31}, [%32];"
            : "=r"(r[0]), "=r"(r[1]), "=r"(r[2]), "=r"(r[3]), "=r"(r[4]), "=r"(r[5]),
              "=r"(r[6]), "=r"(r[7]), "=r"(r[8]), "=r"(r[9]), "=r"(r[10]), "=r"(r[11]),
              "=r"(r[12]), "=r"(r[13]), "=r"(r[14]), "=r"(r[15]), "=r"(r[16]), "=r"(r[17]),
              "=r"(r[18]), "=r"(r[19]), "=r"(r[20]), "=r"(r[21]), "=r"(r[22]), "=r"(r[23]),
              "=r"(r[24]), "=r"(r[25]), "=r"(r[26]), "=r"(r[27]), "=r"(r[28]), "=r"(r[29]),
              "=r"(r[30]), "=r"(r[31])
            : "r"(tmem + cb * 32));
        asm volatile("tcgen05.wait::ld.sync.aligned;" ::: "memory");
        #pragma unroll
        for (int g = 0; g < 8; g++) {
            float4 w = w4[cb * 8 + g];
            float4 o;
            o.x = fminf(fmaxf(fmaf(__uint_as_float(r[4*g+0]), scale, w.x), -2.f), 2.f);
            o.y = fminf(fmaxf(fmaf(__uint_as_float(r[4*g+1]), scale, w.y), -2.f), 2.f);
            o.z = fminf(fmaxf(fmaf(__uint_as_float(r[4*g+2]), scale, w.z), -2.f), 2.f);
            o.w = fminf(fmaxf(fmaf(__uint_as_float(r[4*g+3]), scale, w.w), -2.f), 2.f);
            o4[cb * 8 + g] = o;
        }
    }
    __syncthreads();
    if (wid == 0) {
        asm volatile("tcgen05.relinquish_alloc_permit.cta_group::1.sync.aligned;");
        asm volatile("tcgen05.dealloc.cta_group::1.sync.aligned.b32 %0, %1;" :: "r"(tmem), "r"(128u));
    }
#else
    // -------- mma.sync path (sm_103 non-"a" compatible) ----
    int wm = (wid & 1) * 64;        // warp M offset (warp grid 2x2, warp tile 64x64)
    int wn = (wid >> 1) * 64;       // warp N offset
    const __half* Ag = g_A;
    const __half* Bg = g_B;

    float acc[128];
    #pragma unroll
    for (int i = 0; i < 128; i++) acc[i] = 0.f;

    // stage loader: 128 threads x 16B, 8 iters per operand
    auto load_stage = [&](int s, int kbase) {
        uint32_t a_s = sb + SMEM_DATA0 + s * STAGE_BYTES;
        uint32_t b_s = a_s + A_TILE_BYTES;
        #pragma unroll
        for (int i = 0; i < 8; i++) {
            int id = i * 128 + tid;            // 0..1023
            int row = id >> 3, ch = id & 7;
            uint32_t so = (uint32_t)(row * 128 + ((ch ^ (row & 7)) << 4));
            cpasync16(a_s + so, Ag + (size_t)(m0 + row) * K_TOT + kbase + ch * 8);
            cpasync16(b_s + so, Bg + (size_t)(q0 + row) * K_TOT + kbase + ch * 8);
        }
    };

    load_stage(0, 0);
    asm volatile("cp.async.commit_group;" ::: "memory");
    load_stage(1, CHUNK_K);
    asm volatile("cp.async.commit_group;" ::: "memory");

    int s_cur = 0, s_nxt = 2;
    #pragma unroll 1
    for (int c = 0; c < NCHUNK; c++) {
        asm volatile("cp.async.wait_group 1;" ::: "memory");
        __syncthreads();
        if (c + 2 < NCHUNK) load_stage(s_nxt, (c + 2) * CHUNK_K);
        asm volatile("cp.async.commit_group;" ::: "memory");

        uint32_t a_s = sb + SMEM_DATA0 + s_cur * STAGE_BYTES;
        uint32_t b_s = a_s + A_TILE_BYTES;
        #pragma unroll
        for (int kk = 0; kk < 4; kk++) {
            uint32_t af[4][4], bf[4][4];
            #pragma unroll
            for (int mt = 0; mt < 4; mt++) {
                int m_r = wm + mt * 16 + (lane & 15);
                int kch = kk * 2 + (lane >> 4);
                ldsm4(af[mt][0], af[mt][1], af[mt][2], af[mt][3],
                      a_s + (uint32_t)(m_r * 128 + ((kch ^ (m_r & 7)) << 4)));
            }
            #pragma unroll
            for (int pr = 0; pr < 4; pr++) {
                int g = lane >> 3;
                int n_r = wn + pr * 16 + (lane & 7) + (g >> 1) * 8;
                int kch = kk * 2 + (g & 1);
                ldsm4(bf[pr][0], bf[pr][1], bf[pr][2], bf[pr][3],
                      b_s + (uint32_t)(n_r * 128 + ((kch ^ (n_r & 7)) << 4)));
            }
            #pragma unroll
            for (int mt = 0; mt < 4; mt++) {
                #pragma unroll
                for (int nt = 0; nt < 8; nt++) {
                    int pr = nt >> 1, off = (nt & 1) * 2;
                    mma16816(&acc[(mt * 8 + nt) * 4], af[mt], bf[pr][off], bf[pr][off + 1]);
                }
            }
        }
        s_cur = (s_cur + 1 == NSTAGE) ? 0 : s_cur + 1;
        s_nxt = (s_nxt + 1 == NSTAGE) ? 0 : s_nxt + 1;
    }

    // ---- fused epilogue ----
    float act = (float)g_spike_count * (1.0f / (NBATCH * T_DIM));
    float scale = sqrtf(0.1f / (act + 1e-6f));
    #pragma unroll
    for (int mt = 0; mt < 4; mt++) {
        int r0 = m0 + wm + mt * 16 + (lane >> 2);
        #pragma unroll
        for (int nt = 0; nt < 8; nt++) {
            int cidx = q0 + wn + nt * 8 + (lane & 3) * 2;
            const float* d = &acc[(mt * 8 + nt) * 4];
            {
                const float2 w = *(const float2*)(weights + (size_t)r0 * Q_DIM + cidx);
                float2 o;
                o.x = fminf(fmaxf(fmaf(d[0], scale, w.x), -2.f), 2.f);
                o.y = fminf(fmaxf(fmaf(d[1], scale, w.y), -2.f), 2.f);
                *(float2*)(out + (size_t)r0 * Q_DIM + cidx) = o;
            }
            {
                const float2 w = *(const float2*)(weights + (size_t)(r0 + 8) * Q_DIM + cidx);
                float2 o;
                o.x = fminf(fmaxf(fmaf(d[2], scale, w.x), -2.f), 2.f);
                o.y = fminf(fmaxf(fmaf(d[3], scale, w.y), -2.f), 2.f);
                *(float2*)(out + (size_t)(r0 + 8) * Q_DIM + cidx) = o;
            }
        }
    }
#endif
}

// ================= host =================
typedef CUresult (*tmap_encode_t)(
    CUtensorMap*, CUtensorMapDataType, cuuint32_t, void*,
    const cuuint64_t*, const cuuint64_t*, const cuuint32_t*, const cuuint32_t*,
    CUtensorMapInterleave, CUtensorMapSwizzle, CUtensorMapL2promotion, CUtensorMapFloatOOBfill);

extern "C" void kernel_launch(void* const* d_in, const int* in_sizes, int n_in,
                              void* d_out, int out_size)
{
    const float* pre  = (const float*)d_in[0];
    const float* post = (const float*)d_in[1];
    const float* w    = (const float*)d_in[2];
    const float* ap   = (const float*)d_in[3];
    const float* am   = (const float*)d_in[4];
    float* out = (float*)d_out;

    zero_count_kernel<<<1, 1>>>();
    traces_kernel<<<256, 256>>>(pre, post, ap, am);

    // TMA descriptors (used only if the tcgen05 path compiled; harmless otherwise)
    CUtensorMap tA = {}, tB = {};
    void* pA = nullptr; void* pB = nullptr;
    cudaGetSymbolAddress(&pA, g_A);
    cudaGetSymbolAddress(&pB, g_B);
    void* fnp = nullptr;
    cudaDriverEntryPointQueryResult qres;
    cudaGetDriverEntryPointByVersion("cuTensorMapEncodeTiled", &fnp, 12000,
                                     cudaEnableDefault, &qres);
    if (!fnp)
        cudaGetDriverEntryPoint("cuTensorMapEncodeTiled", &fnp, cudaEnableDefault, &qres);
    if (fnp) {
        tmap_encode_t encode = (tmap_encode_t)fnp;
        cuuint64_t dims[2]    = {(cuuint64_t)K_TOT, (cuuint64_t)P_DIM};
        cuuint64_t strides[1] = {(cuuint64_t)K_TOT * 2};
        cuuint32_t es[2]      = {1, 1};
        cuuint32_t box[2]     = {CHUNK_K, TILE_M};
        encode(&tA, CU_TENSOR_MAP_DATA_TYPE_FLOAT16, 2, pA, dims, strides, box, es,
               CU_TENSOR_MAP_INTERLEAVE_NONE, CU_TENSOR_MAP_SWIZZLE_128B,
               CU_TENSOR_MAP_L2_PROMOTION_L2_128B, CU_TENSOR_MAP_FLOAT_OOB_FILL_NONE);
        encode(&tB, CU_TENSOR_MAP_DATA_TYPE_FLOAT16, 2, pB, dims, strides, box, es,
               CU_TENSOR_MAP_INTERLEAVE_NONE, CU_TENSOR_MAP_SWIZZLE_128B,
               CU_TENSOR_MAP_L2_PROMOTION_L2_128B, CU_TENSOR_MAP_FLOAT_OOB_FILL_NONE);
    }

    cudaFuncSetAttribute(stdp_gemm_kernel, cudaFuncAttributeMaxDynamicSharedMemorySize,
                         SMEM_DYN_BYTES);
    dim3 grid(P_DIM / TILE_M, Q_DIM / TILE_N);   // (16, 16)
    stdp_gemm_kernel<<<grid, 128, SMEM_DYN_BYTES>>>(tA, tB, w, out);
}